// round 16
// baseline (speedup 1.0000x reference)
#include <cuda_runtime.h>
#include <cuda_fp16.h>
#include <cuda_bf16.h>
#include <cstdint>

#define NN 4096
#define FIN 128
#define FF 64
#define HH 8
#define MAXDEG 512
#define LOG2E 1.44269504088896f
#define MSPLIT 2
#define TPB 16                        // m-tiles per block (32 / MSPLIT)

// scratch (allocation-free rule: device globals)
__device__ float  g_feats[HH * NN * FF];     // fp32 [h][n][f] (for scores)
__device__ __half g_featsB[HH * NN * FF];    // fp16 [h][n][f] (MMA B source)
__device__ float  g_sself[HH * NN];          // pre-scaled by log2e
__device__ float  g_sneigh[HH * NN];         // pre-scaled by log2e
__device__ int    g_nbr[NN * MAXDEG];        // sorted neighbor lists (CSR)
__device__ int    g_tcnt[NN * 32];           // edges per (node, 128-m-tile)
__device__ int    g_toff[NN * 32];           // CSR offset of each tile segment
__device__ float  g_part[MSPLIT * HH * NN * FF];  // split-partial weighted sums
__device__ float  g_dsum[MSPLIT * HH * NN];       // split-partial denominators

__device__ __forceinline__ float ex2f(float x) {
    float r; asm("ex2.approx.ftz.f32 %0, %1;" : "=f"(r) : "f"(x)); return r;
}
__device__ __forceinline__ uint32_t smem_u32(const void* p) {
    uint32_t a;
    asm("{ .reg .u64 t; cvta.to.shared.u64 t, %1; cvt.u32.u64 %0, t; }" : "=r"(a) : "l"(p));
    return a;
}
__device__ __forceinline__ void cp16(uint32_t dst, const void* src) {
    asm volatile("cp.async.cg.shared.global [%0], [%1], 16;" :: "r"(dst), "l"(src));
}

// ---------------------------------------------------------------------------
// Kernel A: feats[h] = X @ W[h]. 64x64 tile, 256 thr, 4x4/thread, K-chunk 32.
// Epilogue writes fp32 and fp16 copies.  (proven: 25.2us)
// ---------------------------------------------------------------------------
__global__ __launch_bounds__(256) void gemm_feats_kernel(
    const float* __restrict__ X, const float* __restrict__ W)
{
    __shared__ float Xs[32 * 68];
    __shared__ float Ws[32 * 68];

    const int h  = blockIdx.y;
    const int r0 = blockIdx.x * 64;
    const int tid = threadIdx.x;
    const int tx = tid & 15;
    const int ty = tid >> 4;

    float acc[4][4];
#pragma unroll
    for (int i = 0; i < 4; i++)
#pragma unroll
        for (int j = 0; j < 4; j++) acc[i][j] = 0.0f;

    for (int kc = 0; kc < FIN; kc += 32) {
        for (int i = tid; i < 64 * 8; i += 256) {
            int r = i >> 3, kq = (i & 7) * 4;
            float4 v = *(const float4*)(X + (r0 + r) * FIN + kc + kq);
            Xs[(kq + 0) * 68 + r] = v.x;
            Xs[(kq + 1) * 68 + r] = v.y;
            Xs[(kq + 2) * 68 + r] = v.z;
            Xs[(kq + 3) * 68 + r] = v.w;
        }
        for (int i = tid; i < 32 * 16; i += 256) {
            int k = i >> 4, fq = (i & 15) * 4;
            float4 v = *(const float4*)(W + h * FIN * FF + (kc + k) * FF + fq);
            *(float4*)(Ws + k * 68 + fq) = v;
        }
        __syncthreads();
#pragma unroll
        for (int k = 0; k < 32; k++) {
            float4 a = *(const float4*)(Xs + k * 68 + ty * 4);
            float4 b = *(const float4*)(Ws + k * 68 + tx * 4);
            float av[4] = {a.x, a.y, a.z, a.w};
            float bv[4] = {b.x, b.y, b.z, b.w};
#pragma unroll
            for (int i = 0; i < 4; i++)
#pragma unroll
                for (int j = 0; j < 4; j++) acc[i][j] += av[i] * bv[j];
        }
        __syncthreads();
    }
#pragma unroll
    for (int i = 0; i < 4; i++) {
        int n = r0 + ty * 4 + i;
        *(float4*)(g_feats + (h * NN + n) * FF + tx * 4) =
            make_float4(acc[i][0], acc[i][1], acc[i][2], acc[i][3]);
        __half2 p0 = __floats2half2_rn(acc[i][0], acc[i][1]);
        __half2 p1 = __floats2half2_rn(acc[i][2], acc[i][3]);
        uint2 u = make_uint2(*(uint32_t*)&p0, *(uint32_t*)&p1);
        *(uint2*)(g_featsB + (h * NN + n) * FF + tx * 4) = u;
    }
}

// ---------------------------------------------------------------------------
// Kernel B: scores (pre-scaled by log2e). one warp per (h,n). (proven: 4.6us)
// ---------------------------------------------------------------------------
__global__ __launch_bounds__(256) void score_kernel(
    const float* __restrict__ a_self, const float* __restrict__ a_neigh)
{
    const int warp = threadIdx.x >> 5;
    const int lane = threadIdx.x & 31;
    const int p = blockIdx.x * 8 + warp;       // p = h*NN + n
    const int h = p >> 12;

    float v0 = g_feats[p * FF + lane];
    float v1 = g_feats[p * FF + lane + 32];
    float ss = v0 * a_self[h * FF + lane]  + v1 * a_self[h * FF + lane + 32];
    float sn = v0 * a_neigh[h * FF + lane] + v1 * a_neigh[h * FF + lane + 32];
#pragma unroll
    for (int o = 16; o; o >>= 1) {
        ss += __shfl_xor_sync(0xffffffffu, ss, o);
        sn += __shfl_xor_sync(0xffffffffu, sn, o);
    }
    if (lane == 0) { g_sself[p] = ss * LOG2E; g_sneigh[p] = sn * LOG2E; }
}

// ---------------------------------------------------------------------------
// Kernel C1: sorted neighbor compaction + per-tile counts AND offsets.
// ---------------------------------------------------------------------------
__global__ __launch_bounds__(256) void compact_kernel(const int* __restrict__ A)
{
    const int warp = threadIdx.x >> 5;
    const int lane = threadIdx.x & 31;
    const int n = blockIdx.x * 8 + warp;
    const long long rb = (long long)n * NN;

    int base = 0, tcnt = 0;
    for (int i = 0; i < NN / 32; i++) {
        if ((i & 3) == 0 && lane == 0) g_toff[n * 32 + (i >> 2)] = base;
        int a = A[rb + i * 32 + lane];
        unsigned mask = __ballot_sync(0xffffffffu, a != 0);
        int c = __popc(mask);
        if (a) {
            int pos = base + __popc(mask & ((1u << lane) - 1));
            if (pos < MAXDEG) g_nbr[n * MAXDEG + pos] = i * 32 + lane;
        }
        base += c;
        tcnt += c;
        if ((i & 3) == 3) {
            if (lane == 0) g_tcnt[n * 32 + (i >> 2)] = tcnt;
            tcnt = 0;
        }
    }
}

// ---------------------------------------------------------------------------
// Kernel C2: warp-MMA attention partial aggregation (fp16 HMMA, fp32 accum).
// grid (NN/128 * MSPLIT, HH) = (64, 8), 256 thr, smem 75.3KB -> 3 CTAs/SM.
// n-tile 128, warp tile 32x32 (4 row-blocks x 2 col-halves). Each block does
// 16 m-tiles (one m-split half). Per tile: zero P (data cols only), probe CSR
// via prestaged toff/cnt (2 thr/row), scatter exp2 into padded P; F
// double-buffered via cp.async into XOR-swizzled 128B rows.
// Writes partial sums + denominators; epilogue kernel combines.
// ---------------------------------------------------------------------------
#define PS 136                        // P row stride (halfs); 272B
#define SM_SUM 0                      // float[128]
#define SM_SS  512                    // float[128]
#define SM_SNB 1024                   // float[128]
#define SM_OFF 1536                   // short[128*16] = 4KB
#define SM_CNT 5632                   // uint8[128*16] = 2KB
#define SM_P   7680                   // 128*272 = 34816
#define SM_F0  42496                  // 128*128 = 16384 (swizzled rows)
#define SM_F1  58880
#define SM_TOTAL 75264

__global__ void __launch_bounds__(256, 3) attn_mma_kernel()
{
    extern __shared__ char smem[];
    float*   sSum = (float*)(smem + SM_SUM);
    float*   sSS  = (float*)(smem + SM_SS);
    float*   sSnb = (float*)(smem + SM_SNB);
    short*   sOff = (short*)(smem + SM_OFF);
    uint8_t* sCnt = (uint8_t*)(smem + SM_CNT);
    __half*  sP   = (__half*)(smem + SM_P);
    const uint32_t sb = smem_u32(smem);

    const int tid  = threadIdx.x;
    const int wid  = tid >> 5;
    const int lane = tid & 31;
    const int h     = blockIdx.y;
    const int ntile = blockIdx.x >> 1;
    const int msp   = blockIdx.x & 1;
    const int n0    = ntile * 128;
    const int mt0   = msp * TPB;         // first m-tile index

    const int r0 = (wid & 3) * 32;       // MMA row block (32 rows)
    const int cb = (wid >> 2) * 32;      // MMA col half

    const int prow = tid >> 1;           // probe: row 0..127
    const int psl  = tid & 1;            // probe: slot 0..1
    const int pn   = n0 + prow;

    if (tid < 128) {
        sSum[tid] = 0.0f;
        sSS[tid]  = g_sself[h * NN + n0 + tid];
    }
    // prestage per-tile offsets + counts for this block's 16 tiles
    for (int i = tid; i < 128 * TPB; i += 256) {
        int row = i >> 4, k = i & 15;
        sOff[i] = (short)g_toff[(n0 + row) * 32 + mt0 + k];
        sCnt[i] = (uint8_t)g_tcnt[(n0 + row) * 32 + mt0 + k];
    }

    float d[2][4][4];
#pragma unroll
    for (int rf = 0; rf < 2; rf++)
#pragma unroll
        for (int j = 0; j < 4; j++)
#pragma unroll
            for (int k = 0; k < 4; k++) d[rf][j][k] = 0.0f;

    const float* __restrict__ snb = g_sneigh + h * NN;

    // ldmatrix A base addresses (padded P, proven formula)
    const uint32_t aA0 = sb + SM_P +
        (uint32_t)(((r0 + (lane & 15)) * PS + ((lane >> 4) << 3)) * 2);
    const uint32_t aA1 = aA0 + 16 * PS * 2;
    // F swizzle: row m (128B), chunk q stored at slot q ^ (m & 7)
    const int fRow = lane & 15;          // within-ks row
    const int fSw  = lane & 7;           // = mrow & 7 for any ks
    const int cc0  = (cb >> 3) + (lane >> 4);   // base col-chunk

    // prologue: stage F tile mt0 into F0
    {
        const int mb = mt0 * 128;
#pragma unroll
        for (int it = 0; it < 4; it++) {
            int i = tid + it * 256;
            int m = i >> 3, q = i & 7;
            cp16(sb + SM_F0 + (uint32_t)(m * 128 + ((q ^ (m & 7)) << 4)),
                 g_featsB + (h * NN + mb + m) * FF + q * 8);
        }
        asm volatile("cp.async.commit_group;" ::: "memory");
    }

    for (int lt = 0; lt < TPB; lt++) {
        const int mb = (mt0 + lt) * 128;
        const int buf = lt & 1;

        __syncthreads();   // previous MMA done: P, sSnb, F[buf^1] free

        // --- zero P data columns (skip pad: ldmatrix never reads cols 128+) ---
        for (int i = tid; i < 2048; i += 256) {
            int row = i >> 4, q = i & 15;
            *(int4*)(smem + SM_P + row * (PS * 2) + q * 16) = make_int4(0, 0, 0, 0);
        }
        // --- stage sneigh tile ---
        if (tid < 128) sSnb[tid] = snb[mb + tid];
        __syncthreads();

        // --- probe + scatter (2 threads per row) ---
        {
            int cnt = (int)sCnt[prow * 16 + lt];
            const int* nbp = g_nbr + pn * MAXDEG + (int)sOff[prow * 16 + lt];
            float ssv = sSS[prow];
            float esum = 0.0f;

            // fast path: up to 10 edges per row (5 slots x 2 threads)
            int ms[5];
#pragma unroll
            for (int t = 0; t < 5; t++) {
                int j = psl + t * 2;
                ms[t] = (j < cnt) ? nbp[j] : mb;
            }
#pragma unroll
            for (int t = 0; t < 5; t++) {
                int j = psl + t * 2;
                if (j < cnt) {
                    int col = ms[t] - mb;
                    float sc = ssv + sSnb[col];
                    sc = sc > 0.0f ? sc : 0.2f * sc;
                    float e = ex2f(sc);
                    esum += e;
                    sP[prow * PS + col] = __float2half(e);
                }
            }
            // overflow path
            for (int j = 10 + psl; j < cnt; j += 2) {
                int col = nbp[j] - mb;
                float sc = ssv + sSnb[col];
                sc = sc > 0.0f ? sc : 0.2f * sc;
                float e = ex2f(sc);
                esum += e;
                sP[prow * PS + col] = __float2half(e);
            }
            esum += __shfl_xor_sync(0xffffffffu, esum, 1);
            if (psl == 0) sSum[prow] += esum;
        }

        // --- stage next F tile into other buffer (cross-tile prefetch) ---
        if (lt < TPB - 1) {
            uint32_t fb = sb + (buf ? SM_F0 : SM_F1);
            const int mbn = (mt0 + lt + 1) * 128;
#pragma unroll
            for (int it = 0; it < 4; it++) {
                int i = tid + it * 256;
                int m = i >> 3, q = i & 7;
                cp16(fb + (uint32_t)(m * 128 + ((q ^ (m & 7)) << 4)),
                     g_featsB + (h * NN + mbn + m) * FF + q * 8);
            }
            asm volatile("cp.async.commit_group;" ::: "memory");
            asm volatile("cp.async.wait_group 1;" ::: "memory");
        } else {
            asm volatile("cp.async.wait_group 0;" ::: "memory");
        }
        __syncthreads();   // P scattered + F[buf] arrived

        // --- MMA: D[32,32] += P[32,128] @ F[128,32] ---
        const uint32_t fB = sb + (buf ? SM_F1 : SM_F0);
#pragma unroll
        for (int ks = 0; ks < 8; ks++) {
            uint32_t a0, a1, a2, a3, a4, a5, a6, a7;
            asm volatile("ldmatrix.sync.aligned.m8n8.x4.shared.b16 {%0,%1,%2,%3}, [%4];"
                : "=r"(a0), "=r"(a1), "=r"(a2), "=r"(a3)
                : "r"(aA0 + ks * 32));
            asm volatile("ldmatrix.sync.aligned.m8n8.x4.shared.b16 {%0,%1,%2,%3}, [%4];"
                : "=r"(a4), "=r"(a5), "=r"(a6), "=r"(a7)
                : "r"(aA1 + ks * 32));
            const uint32_t fRowAddr = fB + (uint32_t)((ks * 16 + fRow) * 128);
#pragma unroll
            for (int nf = 0; nf < 2; nf++) {
                uint32_t b0, b1, b2, b3;
                uint32_t bAddr = fRowAddr + (uint32_t)((((cc0 + nf * 2) ^ fSw)) << 4);
                asm volatile("ldmatrix.sync.aligned.m8n8.x4.trans.shared.b16 {%0,%1,%2,%3}, [%4];"
                    : "=r"(b0), "=r"(b1), "=r"(b2), "=r"(b3)
                    : "r"(bAddr));
                asm volatile(
                    "mma.sync.aligned.m16n8k16.row.col.f32.f16.f16.f32 "
                    "{%0,%1,%2,%3}, {%4,%5,%6,%7}, {%8,%9}, {%0,%1,%2,%3};"
                    : "+f"(d[0][nf*2][0]), "+f"(d[0][nf*2][1]), "+f"(d[0][nf*2][2]), "+f"(d[0][nf*2][3])
                    : "r"(a0), "r"(a1), "r"(a2), "r"(a3), "r"(b0), "r"(b1));
                asm volatile(
                    "mma.sync.aligned.m16n8k16.row.col.f32.f16.f16.f32 "
                    "{%0,%1,%2,%3}, {%4,%5,%6,%7}, {%8,%9}, {%0,%1,%2,%3};"
                    : "+f"(d[0][nf*2+1][0]), "+f"(d[0][nf*2+1][1]), "+f"(d[0][nf*2+1][2]), "+f"(d[0][nf*2+1][3])
                    : "r"(a0), "r"(a1), "r"(a2), "r"(a3), "r"(b2), "r"(b3));
                asm volatile(
                    "mma.sync.aligned.m16n8k16.row.col.f32.f16.f16.f32 "
                    "{%0,%1,%2,%3}, {%4,%5,%6,%7}, {%8,%9}, {%0,%1,%2,%3};"
                    : "+f"(d[1][nf*2][0]), "+f"(d[1][nf*2][1]), "+f"(d[1][nf*2][2]), "+f"(d[1][nf*2][3])
                    : "r"(a4), "r"(a5), "r"(a6), "r"(a7), "r"(b0), "r"(b1));
                asm volatile(
                    "mma.sync.aligned.m16n8k16.row.col.f32.f16.f16.f32 "
                    "{%0,%1,%2,%3}, {%4,%5,%6,%7}, {%8,%9}, {%0,%1,%2,%3};"
                    : "+f"(d[1][nf*2+1][0]), "+f"(d[1][nf*2+1][1]), "+f"(d[1][nf*2+1][2]), "+f"(d[1][nf*2+1][3])
                    : "r"(a4), "r"(a5), "r"(a6), "r"(a7), "r"(b2), "r"(b3));
            }
        }
    }
    __syncthreads();

    // --- write partial sums + denominators ---
    {
        float* gp = g_part + (size_t)(msp * HH + h) * NN * FF;
        const int g  = lane >> 2;
        const int cq = (lane & 3) * 2;
#pragma unroll
        for (int rf = 0; rf < 2; rf++) {
            const int rowA = r0 + rf * 16 + g;
            const int rowB = rowA + 8;
#pragma unroll
            for (int nf = 0; nf < 4; nf++) {
                int c = cb + nf * 8 + cq;
                *(float2*)(gp + (n0 + rowA) * FF + c) = make_float2(d[rf][nf][0], d[rf][nf][1]);
                *(float2*)(gp + (n0 + rowB) * FF + c) = make_float2(d[rf][nf][2], d[rf][nf][3]);
            }
        }
    }
    if (tid < 128)
        g_dsum[(msp * HH + h) * NN + n0 + tid] = sSum[tid];
}

// ---------------------------------------------------------------------------
// Kernel D: combine splits, normalize, bias, ELU, store.
// grid 2048, block 256; each thread = one float4 of output.
// ---------------------------------------------------------------------------
__global__ __launch_bounds__(256) void combine_kernel(
    const float* __restrict__ bias, float* __restrict__ out)
{
    const int idx = blockIdx.x * 256 + threadIdx.x;     // quad index
    const int fq = idx & 15;
    const int n  = (idx >> 4) & (NN - 1);
    const int h  = idx >> 16;

    const size_t p = (size_t)(h * NN + n) * FF + fq * 4;
    float4 v0 = *(const float4*)(g_part + p);
    float4 v1 = *(const float4*)(g_part + (size_t)HH * NN * FF + p);
    float ds = g_dsum[h * NN + n] + g_dsum[HH * NN + h * NN + n];
    float inv = 1.0f / ds;
    float4 bv = *(const float4*)(bias + h * FF + fq * 4);

    float4 o;
    o.x = (v0.x + v1.x) * inv + bv.x;
    o.y = (v0.y + v1.y) * inv + bv.y;
    o.z = (v0.z + v1.z) * inv + bv.z;
    o.w = (v0.w + v1.w) * inv + bv.w;
    o.x = o.x > 0.0f ? o.x : expm1f(o.x);
    o.y = o.y > 0.0f ? o.y : expm1f(o.y);
    o.z = o.z > 0.0f ? o.z : expm1f(o.z);
    o.w = o.w > 0.0f ? o.w : expm1f(o.w);

    *(float4*)(out + n * (HH * FF) + h * FF + fq * 4) = o;
}

// ---------------------------------------------------------------------------
extern "C" void kernel_launch(void* const* d_in, const int* in_sizes, int n_in,
                              void* d_out, int out_size)
{
    const float* X       = (const float*)d_in[0];   // [4096,128]
    const int*   A       = (const int*)  d_in[1];   // [4096,4096]
    const float* W       = (const float*)d_in[2];   // [8,128,64]
    const float* b       = (const float*)d_in[3];   // [8,64]
    const float* a_self  = (const float*)d_in[4];   // [8,64]
    const float* a_neigh = (const float*)d_in[5];   // [8,64]
    float* out = (float*)d_out;                     // [4096, 512]

    static bool attr_set = false;
    if (!attr_set) {
        cudaFuncSetAttribute(attn_mma_kernel,
                             cudaFuncAttributeMaxDynamicSharedMemorySize, SM_TOTAL);
        attr_set = true;
    }

    gemm_feats_kernel<<<dim3(NN / 64, HH), 256>>>(X, W);
    score_kernel<<<NN, 256>>>(a_self, a_neigh);
    compact_kernel<<<NN / 8, 256>>>(A);
    attn_mma_kernel<<<dim3((NN / 128) * MSPLIT, HH), 256, SM_TOTAL>>>();
    combine_kernel<<<(NN * HH * FF / 4) / 256, 256>>>(b, out);
}

// round 17
// speedup vs baseline: 1.1370x; 1.1370x over previous
#include <cuda_runtime.h>
#include <cuda_fp16.h>
#include <cuda_bf16.h>
#include <cstdint>

#define NN 4096
#define FIN 128
#define FF 64
#define HH 8
#define MAXDEG 512
#define LOG2E 1.44269504088896f
#define MSPLIT 2
#define TPB 16                        // m-tiles per block (32 / MSPLIT)

// scratch (allocation-free rule: device globals)
__device__ __half g_X16[NN * FIN];           // fp16 X
__device__ __half g_W16[HH * FIN * FF];      // fp16 W
__device__ __half g_featsB[HH * NN * FF];    // fp16 [h][n][f] feats
__device__ float  g_sself[HH * NN];          // pre-scaled by log2e
__device__ float  g_sneigh[HH * NN];         // pre-scaled by log2e
__device__ int    g_nbr[NN * MAXDEG];        // sorted neighbor lists (CSR)
__device__ int    g_tcnt[NN * 32];           // edges per (node, 128-m-tile)
__device__ int    g_toff[NN * 32];           // CSR offset of each tile segment
__device__ float  g_part[MSPLIT * HH * NN * FF];  // split-partial weighted sums
__device__ float  g_dsum[MSPLIT * HH * NN];       // split-partial denominators

__device__ __forceinline__ float ex2f(float x) {
    float r; asm("ex2.approx.ftz.f32 %0, %1;" : "=f"(r) : "f"(x)); return r;
}
__device__ __forceinline__ uint32_t smem_u32(const void* p) {
    uint32_t a;
    asm("{ .reg .u64 t; cvta.to.shared.u64 t, %1; cvt.u32.u64 %0, t; }" : "=r"(a) : "l"(p));
    return a;
}
__device__ __forceinline__ void cp16(uint32_t dst, const void* src) {
    asm volatile("cp.async.cg.shared.global [%0], [%1], 16;" :: "r"(dst), "l"(src));
}

// ---------------------------------------------------------------------------
// Kernel 0: fp32 -> fp16 conversion of X and W.
// ---------------------------------------------------------------------------
#define XQ (NN * FIN / 4)       // 131072 quads
#define WQ (HH * FIN * FF / 4)  // 16384 quads
__global__ __launch_bounds__(256) void convert_kernel(
    const float* __restrict__ X, const float* __restrict__ W)
{
    int i = blockIdx.x * 256 + threadIdx.x;
    if (i < XQ) {
        float4 v = ((const float4*)X)[i];
        __half2 p0 = __floats2half2_rn(v.x, v.y);
        __half2 p1 = __floats2half2_rn(v.z, v.w);
        ((uint2*)g_X16)[i] = make_uint2(*(uint32_t*)&p0, *(uint32_t*)&p1);
    } else if (i < XQ + WQ) {
        int j = i - XQ;
        float4 v = ((const float4*)W)[j];
        __half2 p0 = __floats2half2_rn(v.x, v.y);
        __half2 p1 = __floats2half2_rn(v.z, v.w);
        ((uint2*)g_W16)[j] = make_uint2(*(uint32_t*)&p0, *(uint32_t*)&p1);
    }
}

// ---------------------------------------------------------------------------
// Kernel A: feats[h] = X @ W[h] via fp16 HMMA (fp32 accumulate).
// grid (NN/64, HH) = (512). Block 256 (8 warps; warp tile 16x32).
// Xs: [64 rows][128 k] fp16, padded stride 136 (attn P layout).
// Ws: [128 k][64 f] fp16, XOR-swizzled 128B rows (attn F layout).
// K=128 staged once; 8 k-steps of m16n8k16.
// ---------------------------------------------------------------------------
#define GPS 136                       // Xs row stride (halfs)
__global__ __launch_bounds__(256) void gemm16_kernel()
{
    __shared__ __half Xs[64 * GPS];   // 17408 B
    __shared__ __half Ws[128 * 64];   // 16384 B (swizzled rows)

    const int h  = blockIdx.y;
    const int n0 = blockIdx.x * 64;
    const int tid  = threadIdx.x;
    const int wid  = tid >> 5;
    const int lane = tid & 31;

    const int r0 = (wid & 3) * 16;        // warp row block
    const int cb = (wid >> 2) * 32;       // warp col half

    const uint32_t sbX = smem_u32(Xs);
    const uint32_t sbW = smem_u32(Ws);

    // stage Xs: 64 rows x 16 chunks of 16B
#pragma unroll
    for (int it = 0; it < 4; it++) {
        int i = tid + it * 256;
        int r = i >> 4, q = i & 15;
        cp16(sbX + (uint32_t)(r * (GPS * 2) + q * 16),
             g_X16 + (n0 + r) * FIN + q * 8);
    }
    // stage Ws: 128 rows x 8 chunks, swizzled
#pragma unroll
    for (int it = 0; it < 4; it++) {
        int i = tid + it * 256;
        int k = i >> 3, q = i & 7;
        cp16(sbW + (uint32_t)(k * 128 + ((q ^ (k & 7)) << 4)),
             g_W16 + h * FIN * FF + k * FF + q * 8);
    }
    asm volatile("cp.async.commit_group;" ::: "memory");
    asm volatile("cp.async.wait_group 0;" ::: "memory");
    __syncthreads();

    float d[4][4];
#pragma unroll
    for (int j = 0; j < 4; j++)
#pragma unroll
        for (int k = 0; k < 4; k++) d[j][k] = 0.0f;

    const uint32_t aA0 = sbX +
        (uint32_t)(((r0 + (lane & 15)) * GPS + ((lane >> 4) << 3)) * 2);
    const int fRow = lane & 15;
    const int fSw  = lane & 7;
    const int cc0  = (cb >> 3) + (lane >> 4);

#pragma unroll
    for (int ks = 0; ks < 8; ks++) {
        uint32_t a0, a1, a2, a3;
        asm volatile("ldmatrix.sync.aligned.m8n8.x4.shared.b16 {%0,%1,%2,%3}, [%4];"
            : "=r"(a0), "=r"(a1), "=r"(a2), "=r"(a3)
            : "r"(aA0 + ks * 32));
        const uint32_t fRowAddr = sbW + (uint32_t)((ks * 16 + fRow) * 128);
#pragma unroll
        for (int nf = 0; nf < 2; nf++) {
            uint32_t b0, b1, b2, b3;
            uint32_t bAddr = fRowAddr + (uint32_t)((((cc0 + nf * 2) ^ fSw)) << 4);
            asm volatile("ldmatrix.sync.aligned.m8n8.x4.trans.shared.b16 {%0,%1,%2,%3}, [%4];"
                : "=r"(b0), "=r"(b1), "=r"(b2), "=r"(b3)
                : "r"(bAddr));
            asm volatile(
                "mma.sync.aligned.m16n8k16.row.col.f32.f16.f16.f32 "
                "{%0,%1,%2,%3}, {%4,%5,%6,%7}, {%8,%9}, {%0,%1,%2,%3};"
                : "+f"(d[nf*2][0]), "+f"(d[nf*2][1]), "+f"(d[nf*2][2]), "+f"(d[nf*2][3])
                : "r"(a0), "r"(a1), "r"(a2), "r"(a3), "r"(b0), "r"(b1));
            asm volatile(
                "mma.sync.aligned.m16n8k16.row.col.f32.f16.f16.f32 "
                "{%0,%1,%2,%3}, {%4,%5,%6,%7}, {%8,%9}, {%0,%1,%2,%3};"
                : "+f"(d[nf*2+1][0]), "+f"(d[nf*2+1][1]), "+f"(d[nf*2+1][2]), "+f"(d[nf*2+1][3])
                : "r"(a0), "r"(a1), "r"(a2), "r"(a3), "r"(b2), "r"(b3));
        }
    }

    // epilogue: fp16 feats
    {
        const int g  = lane >> 2;
        const int cq = (lane & 3) * 2;
        const int rowA = r0 + g;
        const int rowB = rowA + 8;
#pragma unroll
        for (int nf = 0; nf < 4; nf++) {
            int c = cb + nf * 8 + cq;
            __half2 pA = __floats2half2_rn(d[nf][0], d[nf][1]);
            __half2 pB = __floats2half2_rn(d[nf][2], d[nf][3]);
            *(uint32_t*)(g_featsB + (h * NN + n0 + rowA) * FF + c) = *(uint32_t*)&pA;
            *(uint32_t*)(g_featsB + (h * NN + n0 + rowB) * FF + c) = *(uint32_t*)&pB;
        }
    }
}

// ---------------------------------------------------------------------------
// Kernel B: scores (pre-scaled by log2e) from fp16 feats. one warp per (h,n).
// ---------------------------------------------------------------------------
__global__ __launch_bounds__(256) void score_kernel(
    const float* __restrict__ a_self, const float* __restrict__ a_neigh)
{
    const int warp = threadIdx.x >> 5;
    const int lane = threadIdx.x & 31;
    const int p = blockIdx.x * 8 + warp;       // p = h*NN + n
    const int h = p >> 12;

    float2 fv = __half22float2(((const __half2*)(g_featsB + p * FF))[lane]);
    const int f0 = lane * 2;
    float ss = fv.x * a_self[h * FF + f0]  + fv.y * a_self[h * FF + f0 + 1];
    float sn = fv.x * a_neigh[h * FF + f0] + fv.y * a_neigh[h * FF + f0 + 1];
#pragma unroll
    for (int o = 16; o; o >>= 1) {
        ss += __shfl_xor_sync(0xffffffffu, ss, o);
        sn += __shfl_xor_sync(0xffffffffu, sn, o);
    }
    if (lane == 0) { g_sself[p] = ss * LOG2E; g_sneigh[p] = sn * LOG2E; }
}

// ---------------------------------------------------------------------------
// Kernel C1: sorted neighbor compaction + per-tile counts AND offsets.
// ---------------------------------------------------------------------------
__global__ __launch_bounds__(256) void compact_kernel(const int* __restrict__ A)
{
    const int warp = threadIdx.x >> 5;
    const int lane = threadIdx.x & 31;
    const int n = blockIdx.x * 8 + warp;
    const long long rb = (long long)n * NN;

    int base = 0, tcnt = 0;
    for (int i = 0; i < NN / 32; i++) {
        if ((i & 3) == 0 && lane == 0) g_toff[n * 32 + (i >> 2)] = base;
        int a = A[rb + i * 32 + lane];
        unsigned mask = __ballot_sync(0xffffffffu, a != 0);
        int c = __popc(mask);
        if (a) {
            int pos = base + __popc(mask & ((1u << lane) - 1));
            if (pos < MAXDEG) g_nbr[n * MAXDEG + pos] = i * 32 + lane;
        }
        base += c;
        tcnt += c;
        if ((i & 3) == 3) {
            if (lane == 0) g_tcnt[n * 32 + (i >> 2)] = tcnt;
            tcnt = 0;
        }
    }
}

// ---------------------------------------------------------------------------
// Kernel C2: warp-MMA attention partial aggregation (R15 config, measured
// 89.7us). grid (NN/128 * MSPLIT, HH) = (64, 8), 256 thr.
// ---------------------------------------------------------------------------
#define PS 136                        // P row stride (halfs); 272B
#define SM_SUM 0                      // float[128]
#define SM_SS  512                    // float[128]
#define SM_SNB 1024                   // float[128]
#define SM_OFF 1536                   // short[128*16]
#define SM_CNT 5632                   // short[128*16]
#define SM_P   9728                   // 128*272 = 34816
#define SM_F0  44544                  // 128*128 = 16384 (swizzled rows)
#define SM_F1  60928
#define SM_TOTAL 77312

__global__ void __launch_bounds__(256, 3) attn_mma_kernel()
{
    extern __shared__ char smem[];
    float*  sSum = (float*)(smem + SM_SUM);
    float*  sSS  = (float*)(smem + SM_SS);
    float*  sSnb = (float*)(smem + SM_SNB);
    short*  sOff = (short*)(smem + SM_OFF);
    short*  sCnt = (short*)(smem + SM_CNT);
    __half* sP   = (__half*)(smem + SM_P);
    const uint32_t sb = smem_u32(smem);

    const int tid  = threadIdx.x;
    const int wid  = tid >> 5;
    const int lane = tid & 31;
    const int h     = blockIdx.y;
    const int ntile = blockIdx.x >> 1;
    const int msp   = blockIdx.x & 1;
    const int n0    = ntile * 128;
    const int mt0   = msp * TPB;

    const int r0 = (wid & 3) * 32;
    const int cb = (wid >> 2) * 32;

    const int prow = tid >> 1;
    const int psl  = tid & 1;
    const int pn   = n0 + prow;

    if (tid < 128) {
        sSum[tid] = 0.0f;
        sSS[tid]  = g_sself[h * NN + n0 + tid];
    }
    for (int i = tid; i < 128 * TPB; i += 256) {
        int row = i >> 4, k = i & 15;
        sOff[i] = (short)g_toff[(n0 + row) * 32 + mt0 + k];
        sCnt[i] = (short)g_tcnt[(n0 + row) * 32 + mt0 + k];
    }

    float d[2][4][4];
#pragma unroll
    for (int rf = 0; rf < 2; rf++)
#pragma unroll
        for (int j = 0; j < 4; j++)
#pragma unroll
            for (int k = 0; k < 4; k++) d[rf][j][k] = 0.0f;

    const float* __restrict__ snb = g_sneigh + h * NN;

    const uint32_t aA0 = sb + SM_P +
        (uint32_t)(((r0 + (lane & 15)) * PS + ((lane >> 4) << 3)) * 2);
    const uint32_t aA1 = aA0 + 16 * PS * 2;
    const int fRow = lane & 15;
    const int fSw  = lane & 7;
    const int cc0  = (cb >> 3) + (lane >> 4);

    // prologue: stage F tile mt0 into F0
    {
        const int mb = mt0 * 128;
#pragma unroll
        for (int it = 0; it < 4; it++) {
            int i = tid + it * 256;
            int m = i >> 3, q = i & 7;
            cp16(sb + SM_F0 + (uint32_t)(m * 128 + ((q ^ (m & 7)) << 4)),
                 g_featsB + (h * NN + mb + m) * FF + q * 8);
        }
        asm volatile("cp.async.commit_group;" ::: "memory");
    }

    for (int lt = 0; lt < TPB; lt++) {
        const int mb = (mt0 + lt) * 128;
        const int buf = lt & 1;

        __syncthreads();

        for (int i = tid; i < 2176; i += 256)
            *(int4*)(smem + SM_P + i * 16) = make_int4(0, 0, 0, 0);
        if (tid < 128) sSnb[tid] = snb[mb + tid];
        __syncthreads();

        // --- probe + scatter (2 threads per row) ---
        {
            int cnt = (int)sCnt[prow * 16 + lt];
            const int* nbp = g_nbr + pn * MAXDEG + (int)sOff[prow * 16 + lt];
            float ssv = sSS[prow];
            float esum = 0.0f;

            int ms[5];
#pragma unroll
            for (int t = 0; t < 5; t++) {
                int j = psl + t * 2;
                ms[t] = (j < cnt) ? nbp[j] : mb;
            }
#pragma unroll
            for (int t = 0; t < 5; t++) {
                int j = psl + t * 2;
                if (j < cnt) {
                    int col = ms[t] - mb;
                    float sc = ssv + sSnb[col];
                    sc = sc > 0.0f ? sc : 0.2f * sc;
                    float e = ex2f(sc);
                    esum += e;
                    sP[prow * PS + col] = __float2half(e);
                }
            }
            for (int j = 10 + psl; j < cnt; j += 2) {
                int col = nbp[j] - mb;
                float sc = ssv + sSnb[col];
                sc = sc > 0.0f ? sc : 0.2f * sc;
                float e = ex2f(sc);
                esum += e;
                sP[prow * PS + col] = __float2half(e);
            }
            esum += __shfl_xor_sync(0xffffffffu, esum, 1);
            if (psl == 0) sSum[prow] += esum;
        }

        if (lt < TPB - 1) {
            uint32_t fb = sb + (buf ? SM_F0 : SM_F1);
            const int mbn = (mt0 + lt + 1) * 128;
#pragma unroll
            for (int it = 0; it < 4; it++) {
                int i = tid + it * 256;
                int m = i >> 3, q = i & 7;
                cp16(fb + (uint32_t)(m * 128 + ((q ^ (m & 7)) << 4)),
                     g_featsB + (h * NN + mbn + m) * FF + q * 8);
            }
            asm volatile("cp.async.commit_group;" ::: "memory");
            asm volatile("cp.async.wait_group 1;" ::: "memory");
        } else {
            asm volatile("cp.async.wait_group 0;" ::: "memory");
        }
        __syncthreads();

        const uint32_t fB = sb + (buf ? SM_F1 : SM_F0);
#pragma unroll
        for (int ks = 0; ks < 8; ks++) {
            uint32_t a0, a1, a2, a3, a4, a5, a6, a7;
            asm volatile("ldmatrix.sync.aligned.m8n8.x4.shared.b16 {%0,%1,%2,%3}, [%4];"
                : "=r"(a0), "=r"(a1), "=r"(a2), "=r"(a3)
                : "r"(aA0 + ks * 32));
            asm volatile("ldmatrix.sync.aligned.m8n8.x4.shared.b16 {%0,%1,%2,%3}, [%4];"
                : "=r"(a4), "=r"(a5), "=r"(a6), "=r"(a7)
                : "r"(aA1 + ks * 32));
            const uint32_t fRowAddr = fB + (uint32_t)((ks * 16 + fRow) * 128);
#pragma unroll
            for (int nf = 0; nf < 2; nf++) {
                uint32_t b0, b1, b2, b3;
                uint32_t bAddr = fRowAddr + (uint32_t)((((cc0 + nf * 2) ^ fSw)) << 4);
                asm volatile("ldmatrix.sync.aligned.m8n8.x4.trans.shared.b16 {%0,%1,%2,%3}, [%4];"
                    : "=r"(b0), "=r"(b1), "=r"(b2), "=r"(b3)
                    : "r"(bAddr));
                asm volatile(
                    "mma.sync.aligned.m16n8k16.row.col.f32.f16.f16.f32 "
                    "{%0,%1,%2,%3}, {%4,%5,%6,%7}, {%8,%9}, {%0,%1,%2,%3};"
                    : "+f"(d[0][nf*2][0]), "+f"(d[0][nf*2][1]), "+f"(d[0][nf*2][2]), "+f"(d[0][nf*2][3])
                    : "r"(a0), "r"(a1), "r"(a2), "r"(a3), "r"(b0), "r"(b1));
                asm volatile(
                    "mma.sync.aligned.m16n8k16.row.col.f32.f16.f16.f32 "
                    "{%0,%1,%2,%3}, {%4,%5,%6,%7}, {%8,%9}, {%0,%1,%2,%3};"
                    : "+f"(d[0][nf*2+1][0]), "+f"(d[0][nf*2+1][1]), "+f"(d[0][nf*2+1][2]), "+f"(d[0][nf*2+1][3])
                    : "r"(a0), "r"(a1), "r"(a2), "r"(a3), "r"(b2), "r"(b3));
                asm volatile(
                    "mma.sync.aligned.m16n8k16.row.col.f32.f16.f16.f32 "
                    "{%0,%1,%2,%3}, {%4,%5,%6,%7}, {%8,%9}, {%0,%1,%2,%3};"
                    : "+f"(d[1][nf*2][0]), "+f"(d[1][nf*2][1]), "+f"(d[1][nf*2][2]), "+f"(d[1][nf*2][3])
                    : "r"(a4), "r"(a5), "r"(a6), "r"(a7), "r"(b0), "r"(b1));
                asm volatile(
                    "mma.sync.aligned.m16n8k16.row.col.f32.f16.f16.f32 "
                    "{%0,%1,%2,%3}, {%4,%5,%6,%7}, {%8,%9}, {%0,%1,%2,%3};"
                    : "+f"(d[1][nf*2+1][0]), "+f"(d[1][nf*2+1][1]), "+f"(d[1][nf*2+1][2]), "+f"(d[1][nf*2+1][3])
                    : "r"(a4), "r"(a5), "r"(a6), "r"(a7), "r"(b2), "r"(b3));
            }
        }
    }
    __syncthreads();

    // --- write partial sums + denominators ---
    {
        float* gp = g_part + (size_t)(msp * HH + h) * NN * FF;
        const int g  = lane >> 2;
        const int cq = (lane & 3) * 2;
#pragma unroll
        for (int rf = 0; rf < 2; rf++) {
            const int rowA = r0 + rf * 16 + g;
            const int rowB = rowA + 8;
#pragma unroll
            for (int nf = 0; nf < 4; nf++) {
                int c = cb + nf * 8 + cq;
                *(float2*)(gp + (n0 + rowA) * FF + c) = make_float2(d[rf][nf][0], d[rf][nf][1]);
                *(float2*)(gp + (n0 + rowB) * FF + c) = make_float2(d[rf][nf][2], d[rf][nf][3]);
            }
        }
    }
    if (tid < 128)
        g_dsum[(msp * HH + h) * NN + n0 + tid] = sSum[tid];
}

// ---------------------------------------------------------------------------
// Kernel D: combine splits, normalize, bias, ELU, store.
// ---------------------------------------------------------------------------
__global__ __launch_bounds__(256) void combine_kernel(
    const float* __restrict__ bias, float* __restrict__ out)
{
    const int idx = blockIdx.x * 256 + threadIdx.x;
    const int fq = idx & 15;
    const int n  = (idx >> 4) & (NN - 1);
    const int h  = idx >> 16;

    const size_t p = (size_t)(h * NN + n) * FF + fq * 4;
    float4 v0 = *(const float4*)(g_part + p);
    float4 v1 = *(const float4*)(g_part + (size_t)HH * NN * FF + p);
    float ds = g_dsum[h * NN + n] + g_dsum[HH * NN + h * NN + n];
    float inv = 1.0f / ds;
    float4 bv = *(const float4*)(bias + h * FF + fq * 4);

    float4 o;
    o.x = (v0.x + v1.x) * inv + bv.x;
    o.y = (v0.y + v1.y) * inv + bv.y;
    o.z = (v0.z + v1.z) * inv + bv.z;
    o.w = (v0.w + v1.w) * inv + bv.w;
    o.x = o.x > 0.0f ? o.x : expm1f(o.x);
    o.y = o.y > 0.0f ? o.y : expm1f(o.y);
    o.z = o.z > 0.0f ? o.z : expm1f(o.z);
    o.w = o.w > 0.0f ? o.w : expm1f(o.w);

    *(float4*)(out + n * (HH * FF) + h * FF + fq * 4) = o;
}

// ---------------------------------------------------------------------------
extern "C" void kernel_launch(void* const* d_in, const int* in_sizes, int n_in,
                              void* d_out, int out_size)
{
    const float* X       = (const float*)d_in[0];   // [4096,128]
    const int*   A       = (const int*)  d_in[1];   // [4096,4096]
    const float* W       = (const float*)d_in[2];   // [8,128,64]
    const float* b       = (const float*)d_in[3];   // [8,64]
    const float* a_self  = (const float*)d_in[4];   // [8,64]
    const float* a_neigh = (const float*)d_in[5];   // [8,64]
    float* out = (float*)d_out;                     // [4096, 512]

    static bool attr_set = false;
    if (!attr_set) {
        cudaFuncSetAttribute(attn_mma_kernel,
                             cudaFuncAttributeMaxDynamicSharedMemorySize, SM_TOTAL);
        attr_set = true;
    }

    convert_kernel<<<(XQ + WQ + 255) / 256, 256>>>(X, W);
    gemm16_kernel<<<dim3(NN / 64, HH), 256>>>();
    score_kernel<<<NN, 256>>>(a_self, a_neigh);
    compact_kernel<<<NN / 8, 256>>>(A);
    attn_mma_kernel<<<dim3((NN / 128) * MSPLIT, HH), 256, SM_TOTAL>>>();
    combine_kernel<<<(NN * HH * FF / 4) / 256, 256>>>(b, out);
}